// round 10
// baseline (speedup 1.0000x reference)
#include <cuda_runtime.h>
#include <cuda_fp16.h>

#define NPAIR 8192              // 16384 images as 8192 pairs

// Layouts (pair-interleaved, position-major):
//  g_h1: [pair][196][16] half2  (102 MB)   half2 = (img0, img1) per channel
//  g_h2: [pair][169][32] half2  (177 MB)

__device__ __half2 g_h1[(size_t)NPAIR * 196 * 16];
__device__ __half2 g_h2[(size_t)NPAIR * 169 * 32];
__device__ float g_fcwp[64 * 169 * 12];   // fc_w packed [c3][p][j(10)+pad2]
__device__ float g_s1[32];      // sum[16], sumsq[16]
__device__ float g_s2[64];      // sum[32], sumsq[32]
__device__ float g_gram[1024];  // M[32][32]
__device__ float g_sumA[32];    // A[k]

// ---------------- f32x2 helpers ----------------
typedef unsigned long long ull;
__device__ __forceinline__ ull pk2(float a, float b) {
    ull r; asm("mov.b64 %0, {%1, %2};" : "=l"(r) : "f"(a), "f"(b)); return r;
}
__device__ __forceinline__ void upk2(ull v, float& a, float& b) {
    asm("mov.b64 {%0, %1}, %2;" : "=f"(a), "=f"(b) : "l"(v));
}
#define FMA2(d, a, b) asm("fma.rn.f32x2 %0, %1, %2, %0;" : "+l"(d) : "l"(a), "l"(b))

// ---------------- zero accumulators ----------------
__global__ void k_zero() {
    int t = threadIdx.x;
    g_gram[t] = 0.f;
    if (t < 32) { g_s1[t] = 0.f; g_sumA[t] = 0.f; }
    if (t < 64) g_s2[t] = 0.f;
}

// ---------------- pack fc_w -> [c3][p][12] ----------------
__global__ void k_packfc(const float* __restrict__ fc_w) {
    int i = blockIdx.x * 256 + threadIdx.x;
    if (i >= 10816) return;           // i = c3*169 + p
#pragma unroll
    for (int j = 0; j < 10; j++) g_fcwp[i * 12 + j] = fc_w[(size_t)j * 10816 + i];
    g_fcwp[i * 12 + 10] = 0.f;
    g_fcwp[i * 12 + 11] = 0.f;
}

// ---------------- conv1 (3x3), both images per thread, fp16 out + stats1 ----------------
__global__ __launch_bounds__(256) void k_conv1(const float* __restrict__ x,
                                               const float* __restrict__ w1) {
    __shared__ float s_w[144];
    __shared__ float s_in[512];
    __shared__ float s_red[256];
    int t = threadIdx.x;
    if (t < 144) s_w[t] = w1[t];
    int c = t & 15, chunk = t >> 4;   // 16 chunks over 196 positions
    __syncthreads();
    const float* wc = &s_w[c * 9];
    float w00 = wc[0], w01 = wc[1], w02 = wc[2];
    float w10 = wc[3], w11 = wc[4], w12 = wc[5];
    float w20 = wc[6], w21 = wc[7], w22 = wc[8];
    float ls = 0.f, lsq = 0.f;
    int pair0 = blockIdx.x * 4;

    for (int pp = 0; pp < 4; pp++) {
        int pair = pair0 + pp;
        __syncthreads();
        const float* xp = x + (size_t)pair * 512;
        s_in[t] = xp[t];
        s_in[256 + t] = xp[256 + t];
        __syncthreads();
        __half2* dst = &g_h1[(size_t)pair * 3136];
        for (int p = chunk; p < 196; p += 16) {
            int y = p / 14, xx = p - y * 14;
            const float* r0 = &s_in[y * 16 + xx];
            const float* r1 = r0 + 256;
            float a0 = r0[0]  * w00 + r0[1]  * w01 + r0[2]  * w02
                     + r0[16] * w10 + r0[17] * w11 + r0[18] * w12
                     + r0[32] * w20 + r0[33] * w21 + r0[34] * w22;
            float a1 = r1[0]  * w00 + r1[1]  * w01 + r1[2]  * w02
                     + r1[16] * w10 + r1[17] * w11 + r1[18] * w12
                     + r1[32] * w20 + r1[33] * w21 + r1[34] * w22;
            __half2 hv = __floats2half2_rn(a0, a1);
            __stwt(&dst[p * 16 + c], hv);
            // stats on stored (rounded) values to match what conv2 consumes
            float b0 = __half2float(__low2half(hv));
            float b1 = __half2float(__high2half(hv));
            ls += b0 + b1; lsq += b0 * b0 + b1 * b1;
        }
    }
    __syncthreads();
    s_red[t] = ls;
    __syncthreads();
    if (t < 16) { float s = 0.f; for (int j = 0; j < 16; j++) s += s_red[t + 16 * j];
                  atomicAdd(&g_s1[t], s); }
    __syncthreads();
    s_red[t] = lsq;
    __syncthreads();
    if (t < 16) { float s = 0.f; for (int j = 0; j < 16; j++) s += s_red[t + 16 * j];
                  atomicAdd(&g_s1[16 + t], s); }
}

// ---------------- bn1+relu -> conv2 (2x2) via channel-packed f32x2 ----------------
// bn1 computed per-CTA from g_s1. Weights: 32 ull (64 regs, no duplication).
// s_a layout: [196 pos][2 img][16 ch].
__global__ __launch_bounds__(256) void k_conv2(const float* __restrict__ w2,
                                               const float* __restrict__ g1,
                                               const float* __restrict__ b1) {
    __shared__ __align__(16) float s_a[196 * 32];
    __shared__ float s_red[256];
    __shared__ float s_bn[32];
    int t = threadIdx.x;
    if (t < 16) {
        float n = 16384.f * 196.f;
        float mean = g_s1[t] / n;
        float var  = g_s1[16 + t] / n - mean * mean;
        float sc   = g1[t] * rsqrtf(var + 1e-5f);
        s_bn[t] = sc;
        s_bn[16 + t] = b1[t] - mean * sc;
    }
    int c2 = t & 31, chunk = t >> 5;   // 8 chunks over 169 positions
    // channel-pair packed weights: wp[h*4+q] = (w[c2][2h][q], w[c2][2h+1][q])
    ull wp[32];
    {
        const float* ws = w2 + c2 * 64;   // [c1][ky][kx] for this c2
#pragma unroll
        for (int h = 0; h < 8; h++)
#pragma unroll
            for (int q = 0; q < 4; q++)
                wp[h * 4 + q] = pk2(ws[(2 * h) * 4 + q], ws[(2 * h + 1) * 4 + q]);
    }
    float ls = 0.f, lsq = 0.f;
    int pair0 = blockIdx.x * 4;

    for (int pp = 0; pp < 4; pp++) {
        int pair = pair0 + pp;
        __syncthreads();
        const __half2* src = &g_h1[(size_t)pair * 3136];
        for (int i = t; i < 3136; i += 256) {
            float2 v = __half22float2(src[i]);
            int p = i >> 4, c = i & 15;
            float sc = s_bn[c], bi = s_bn[16 + c];
            s_a[p * 32 + c]      = fmaxf(fmaf(v.x, sc, bi), 0.f);   // img0
            s_a[p * 32 + 16 + c] = fmaxf(fmaf(v.y, sc, bi), 0.f);   // img1
        }
        __syncthreads();
        __half2* dst = &g_h2[(size_t)pair * 5408];
        const ulonglong2* ap2 = reinterpret_cast<const ulonglong2*>(s_a);
        // pos stride = 8 ull2; img stride = 4 ull2
        for (int p = chunk; p < 169; p += 8) {
            int y = p / 13, xx = p - y * 13;
            int b00 = (y * 14 + xx) * 8;
            int b01 = b00 + 8, b10 = b00 + 112, b11 = b00 + 120;
            float outv[2];
#pragma unroll
            for (int img = 0; img < 2; img++) {
                int off = img * 4;
                ull c0 = pk2(0.f, 0.f), c1 = c0, c2a = c0, c3a = c0;
#pragma unroll
                for (int hh = 0; hh < 4; hh++) {
                    ulonglong2 A00 = ap2[b00 + off + hh];
                    ulonglong2 A01 = ap2[b01 + off + hh];
                    ulonglong2 A10 = ap2[b10 + off + hh];
                    ulonglong2 A11 = ap2[b11 + off + hh];
                    FMA2(c0,  A00.x, wp[8 * hh + 0]);
                    FMA2(c1,  A01.x, wp[8 * hh + 1]);
                    FMA2(c2a, A10.x, wp[8 * hh + 2]);
                    FMA2(c3a, A11.x, wp[8 * hh + 3]);
                    FMA2(c0,  A00.y, wp[8 * hh + 4]);
                    FMA2(c1,  A01.y, wp[8 * hh + 5]);
                    FMA2(c2a, A10.y, wp[8 * hh + 6]);
                    FMA2(c3a, A11.y, wp[8 * hh + 7]);
                }
                float l0, h0, l1, h1, l2, h2, l3, h3;
                upk2(c0, l0, h0); upk2(c1, l1, h1);
                upk2(c2a, l2, h2); upk2(c3a, l3, h3);
                outv[img] = ((l0 + h0) + (l1 + h1)) + ((l2 + h2) + (l3 + h3));
            }
            __half2 hv = __floats2half2_rn(outv[0], outv[1]);
            dst[p * 32 + c2] = hv;
            float b0 = __half2float(__low2half(hv));
            float b1 = __half2float(__high2half(hv));
            ls += b0 + b1; lsq += b0 * b0 + b1 * b1;
        }
    }
    __syncthreads();
    s_red[t] = ls;
    __syncthreads();
    if (t < 32) { float s = 0.f; for (int j = 0; j < 8; j++) s += s_red[t + 32 * j];
                  atomicAdd(&g_s2[t], s); }
    __syncthreads();
    s_red[t] = lsq;
    __syncthreads();
    if (t < 32) { float s = 0.f; for (int j = 0; j < 8; j++) s += s_red[t + 32 * j];
                  atomicAdd(&g_s2[32 + t], s); }
}

// ---------------- bn2+relu -> Gram of a2, 4x4 register tiles ----------------
__global__ __launch_bounds__(256) void k_gram(const float* __restrict__ g2,
                                              const float* __restrict__ b2) {
    __shared__ __align__(16) float s_a[169 * 64];   // [p][32ch][2img]
    __shared__ float s_bn[64];
    int t = threadIdx.x;
    if (t < 32) {
        float n = 16384.f * 169.f;
        float mean = g_s2[t] / n;
        float var  = g_s2[32 + t] / n - mean * mean;
        float sc   = g2[t] * rsqrtf(var + 1e-5f);
        s_bn[t] = sc;
        s_bn[32 + t] = b2[t] - mean * sc;
    }
    int slot = t >> 6;          // 4 position slots
    int idx = t & 63;
    int r4 = (idx >> 3) * 4;    // row block
    int c4 = (idx & 7) * 4;     // col block
    ull acc[4][4];
#pragma unroll
    for (int i = 0; i < 4; i++)
#pragma unroll
        for (int j = 0; j < 4; j++) acc[i][j] = pk2(0.f, 0.f);
    ull sA[4] = {pk2(0.f,0.f), pk2(0.f,0.f), pk2(0.f,0.f), pk2(0.f,0.f)};
    const ull one2 = pk2(1.f, 1.f);
    int pair0 = blockIdx.x * 4;

    for (int pp = 0; pp < 4; pp++) {
        __syncthreads();
        const __half2* src = &g_h2[(size_t)(pair0 + pp) * 5408];
        for (int i = t; i < 169 * 32; i += 256) {
            float2 v = __half22float2(src[i]);
            int c = i & 31;
            float sc = s_bn[c], bi = s_bn[32 + c];
            s_a[2 * i]     = fmaxf(fmaf(v.x, sc, bi), 0.f);
            s_a[2 * i + 1] = fmaxf(fmaf(v.y, sc, bi), 0.f);
        }
        __syncthreads();
        const ulonglong2* ap = reinterpret_cast<const ulonglong2*>(s_a);
        for (int p = slot; p < 169; p += 4) {
            ulonglong2 ra = ap[p * 16 + (r4 >> 1)];
            ulonglong2 rb = ap[p * 16 + (r4 >> 1) + 1];
            ulonglong2 ca = ap[p * 16 + (c4 >> 1)];
            ulonglong2 cb = ap[p * 16 + (c4 >> 1) + 1];
            ull rr[4] = {ra.x, ra.y, rb.x, rb.y};
            ull cc[4] = {ca.x, ca.y, cb.x, cb.y};
#pragma unroll
            for (int i = 0; i < 4; i++)
#pragma unroll
                for (int j = 0; j < 4; j++) FMA2(acc[i][j], rr[i], cc[j]);
            if (c4 == 0) {
#pragma unroll
                for (int i = 0; i < 4; i++) FMA2(sA[i], rr[i], one2);
            }
        }
    }
    float lo, hi;
#pragma unroll
    for (int i = 0; i < 4; i++)
#pragma unroll
        for (int j = 0; j < 4; j++) {
            upk2(acc[i][j], lo, hi);
            atomicAdd(&g_gram[(r4 + i) * 32 + c4 + j], lo + hi);
        }
    if (c4 == 0) {
#pragma unroll
        for (int i = 0; i < 4; i++) { upk2(sA[i], lo, hi); atomicAdd(&g_sumA[r4 + i], lo + hi); }
    }
}

// ---------------- bn2+relu -> conv3 (f32x2) -> bn3+relu -> fc (packed fcw) ----------------
// bn2 and bn3 computed per-CTA (bn3 from the Gram matrix).
#define FIN_THREADS 192
__global__ __launch_bounds__(FIN_THREADS) void k_final(const float* __restrict__ w3,
                                                       const float* __restrict__ g2,
                                                       const float* __restrict__ b2,
                                                       const float* __restrict__ g3,
                                                       const float* __restrict__ b3,
                                                       const float* __restrict__ fc_b,
                                                       float* __restrict__ out) {
    extern __shared__ __align__(16) float sm[];
    float* s_a2 = sm;                 // [169][68] padded rows
    float* s_wd = sm + 169 * 68;      // w3 duplicated: [c3][k][2]
    __shared__ float s_m[1024];
    __shared__ float s_A[32];
    __shared__ float s_bn2[64];
    __shared__ float s_bn3[128];
    __shared__ float s_out[20];
    int t = threadIdx.x;
    if (t < 32) {
        float n = 16384.f * 169.f;
        float mean = g_s2[t] / n;
        float var  = g_s2[32 + t] / n - mean * mean;
        float sc   = g2[t] * rsqrtf(var + 1e-5f);
        s_bn2[t] = sc;
        s_bn2[32 + t] = b2[t] - mean * sc;
        s_A[t] = g_sumA[t];
    }
    if (t < 20) s_out[t] = 0.f;
    for (int i = t; i < 1024; i += FIN_THREADS) s_m[i] = g_gram[i];
    for (int i = t; i < 2048; i += FIN_THREADS) {
        float w = w3[i];
        s_wd[2 * i] = w; s_wd[2 * i + 1] = w;
    }
    size_t pair = blockIdx.x;
    const __half2* src = &g_h2[pair * 5408];
    __syncthreads();
    for (int i = t; i < 169 * 32; i += FIN_THREADS) {
        float2 v = __half22float2(src[i]);
        int c = i & 31, p = i >> 5;
        float sc = s_bn2[c], bi = s_bn2[32 + c];
        float2 o;
        o.x = fmaxf(fmaf(v.x, sc, bi), 0.f);
        o.y = fmaxf(fmaf(v.y, sc, bi), 0.f);
        *reinterpret_cast<float2*>(&s_a2[p * 68 + 2 * c]) = o;
    }
    __syncthreads();
    // bn3 from Gram (per-CTA, deterministic): S1 = w.A, S2 = w M w^T
    if (t < 64) {
        float wrow[32];
#pragma unroll
        for (int k = 0; k < 32; k++) wrow[k] = s_wd[(t * 32 + k) * 2];
        float S1 = 0.f, S2 = 0.f;
        for (int k = 0; k < 32; k++) {
            S1 += wrow[k] * s_A[k];
            float inner = 0.f;
#pragma unroll
            for (int kp = 0; kp < 32; kp++) inner += wrow[kp] * s_m[k * 32 + kp];
            S2 += wrow[k] * inner;
        }
        float n = 16384.f * 169.f;
        float mean = S1 / n;
        float var  = S2 / n - mean * mean;
        float sc   = g3[t] * rsqrtf(var + 1e-5f);
        s_bn3[t] = sc;
        s_bn3[64 + t] = b3[t] - mean * sc;
    }
    __syncthreads();

    int lane = t & 31, wid = t >> 5;
    int p = wid * 32 + lane;
    int pc = p < 169 ? p : 168;

    ull a2r[32];
    {
        const ulonglong2* row = reinterpret_cast<const ulonglong2*>(&s_a2[pc * 68]);
#pragma unroll
        for (int i = 0; i < 16; i++) {
            ulonglong2 v = row[i];
            a2r[2 * i] = v.x; a2r[2 * i + 1] = v.y;
        }
    }
    float o0[10], o1[10];
#pragma unroll
    for (int j = 0; j < 10; j++) { o0[j] = 0.f; o1[j] = 0.f; }
    const float4* fwp = reinterpret_cast<const float4*>(g_fcwp);

    for (int c3 = 0; c3 < 64; c3++) {
        const ulonglong2* wr = reinterpret_cast<const ulonglong2*>(&s_wd[c3 * 64]);
        // 4 independent chains of 8 deps
        ull acc0 = pk2(0.f, 0.f), acc1 = acc0, acc2 = acc0, acc3 = acc0;
#pragma unroll
        for (int i = 0; i < 8; i++) {
            ulonglong2 va = wr[2 * i];
            ulonglong2 vb = wr[2 * i + 1];
            FMA2(acc0, a2r[4 * i],     va.x);
            FMA2(acc1, a2r[4 * i + 1], va.y);
            FMA2(acc2, a2r[4 * i + 2], vb.x);
            FMA2(acc3, a2r[4 * i + 3], vb.y);
        }
        float e0, e1, e2, e3, f0, f1, f2, f3;
        upk2(acc0, e0, f0);
        upk2(acc1, e1, f1);
        upk2(acc2, e2, f2);
        upk2(acc3, e3, f3);
        float sc = s_bn3[c3], bi = s_bn3[64 + c3];
        float v0 = fmaxf(fmaf((e0 + e1) + (e2 + e3), sc, bi), 0.f);   // image 0
        float v1 = fmaxf(fmaf((f0 + f1) + (f2 + f3), sc, bi), 0.f);   // image 1
        int base = (c3 * 169 + pc) * 3;
        float4 w0 = fwp[base], w1 = fwp[base + 1], w2 = fwp[base + 2];
        o0[0] += v0 * w0.x; o1[0] += v1 * w0.x;
        o0[1] += v0 * w0.y; o1[1] += v1 * w0.y;
        o0[2] += v0 * w0.z; o1[2] += v1 * w0.z;
        o0[3] += v0 * w0.w; o1[3] += v1 * w0.w;
        o0[4] += v0 * w1.x; o1[4] += v1 * w1.x;
        o0[5] += v0 * w1.y; o1[5] += v1 * w1.y;
        o0[6] += v0 * w1.z; o1[6] += v1 * w1.z;
        o0[7] += v0 * w1.w; o1[7] += v1 * w1.w;
        o0[8] += v0 * w2.x; o1[8] += v1 * w2.x;
        o0[9] += v0 * w2.y; o1[9] += v1 * w2.y;
    }
#pragma unroll
    for (int j = 0; j < 10; j++) {
        if (p >= 169) { o0[j] = 0.f; o1[j] = 0.f; }
#pragma unroll
        for (int off = 16; off > 0; off >>= 1) {
            o0[j] += __shfl_xor_sync(0xffffffffu, o0[j], off);
            o1[j] += __shfl_xor_sync(0xffffffffu, o1[j], off);
        }
    }
    if (lane == 0) {
#pragma unroll
        for (int j = 0; j < 10; j++) {
            atomicAdd(&s_out[j],      o0[j]);
            atomicAdd(&s_out[10 + j], o1[j]);
        }
    }
    __syncthreads();
    if (t < 20) {
        int im = t / 10, j = t - im * 10;
        out[(pair * 2 + im) * 10 + j] = s_out[im * 10 + j] + fc_b[j];
    }
}

// ---------------- launch ----------------
extern "C" void kernel_launch(void* const* d_in, const int* in_sizes, int n_in,
                              void* d_out, int out_size) {
    const float* x    = (const float*)d_in[0];
    const float* w1   = (const float*)d_in[1];
    const float* w2   = (const float*)d_in[2];
    const float* w3   = (const float*)d_in[3];
    const float* g1   = (const float*)d_in[4];
    const float* b1   = (const float*)d_in[5];
    const float* g2   = (const float*)d_in[6];
    const float* b2   = (const float*)d_in[7];
    const float* g3   = (const float*)d_in[8];
    const float* b3   = (const float*)d_in[9];
    const float* fc_w = (const float*)d_in[10];
    const float* fc_b = (const float*)d_in[11];
    float* out = (float*)d_out;

    const int fin_smem = (169 * 68 + 4096) * 4;   // 62352 bytes
    cudaFuncSetAttribute(k_final, cudaFuncAttributeMaxDynamicSharedMemorySize, fin_smem);

    // 6 launches; ncu -s 5 -c 1 captures k_final
    k_zero<<<1, 1024>>>();
    k_packfc<<<43, 256>>>(fc_w);
    k_conv1<<<2048, 256>>>(x, w1);
    k_conv2<<<2048, 256>>>(w2, g1, b1);
    k_gram<<<2048, 256>>>(g2, b2);
    k_final<<<NPAIR, FIN_THREADS, fin_smem>>>(w3, g2, b2, g3, b3, fc_b, out);
}

// round 11
// speedup vs baseline: 1.0865x; 1.0865x over previous
#include <cuda_runtime.h>
#include <cuda_fp16.h>

#define NPAIR 8192              // 16384 images as 8192 pairs

// Layouts (pair-interleaved, position-major):
//  g_h1: [pair][196][16] half2  (102 MB)   half2 = (img0, img1)
//  g_h2: [pair][169][32] half2  (177 MB)   after k_gram: holds a2 = relu(bn2(h2))

__device__ __half2 g_h1[(size_t)NPAIR * 196 * 16];
__device__ __half2 g_h2[(size_t)NPAIR * 169 * 32];
__device__ float g_fcwp[64 * 169 * 12];   // fc_w packed [c3][p][j(10)+pad2]
__device__ float g_part[4 * 16384 * 10];  // fc partials per c3-range
__device__ float g_s1[32];      // sum[16], sumsq[16]
__device__ float g_s2[64];      // sum[32], sumsq[32]
__device__ float g_gram[1024];  // M[32][32]
__device__ float g_sumA[32];    // A[k]
__device__ float g_bn1[32];
__device__ float g_bn2[64];
__device__ float g_bn3[128];

// ---------------- f32x2 helpers ----------------
typedef unsigned long long ull;
__device__ __forceinline__ ull pk2(float a, float b) {
    ull r; asm("mov.b64 %0, {%1, %2};" : "=l"(r) : "f"(a), "f"(b)); return r;
}
__device__ __forceinline__ void upk2(ull v, float& a, float& b) {
    asm("mov.b64 {%0, %1}, %2;" : "=f"(a), "=f"(b) : "l"(v));
}
#define FMA2(d, a, b) asm("fma.rn.f32x2 %0, %1, %2, %0;" : "+l"(d) : "l"(a), "l"(b))

// ---------------- zero accumulators ----------------
__global__ void k_zero() {
    int t = threadIdx.x;
    g_gram[t] = 0.f;
    if (t < 32) { g_s1[t] = 0.f; g_sumA[t] = 0.f; }
    if (t < 64) g_s2[t] = 0.f;
}

// ---------------- pack fc_w -> [c3][p][12] ----------------
__global__ void k_packfc(const float* __restrict__ fc_w) {
    int i = blockIdx.x * 256 + threadIdx.x;
    if (i >= 10816) return;           // i = c3*169 + p
#pragma unroll
    for (int j = 0; j < 10; j++) g_fcwp[i * 12 + j] = fc_w[(size_t)j * 10816 + i];
    g_fcwp[i * 12 + 10] = 0.f;
    g_fcwp[i * 12 + 11] = 0.f;
}

// ---------------- conv1 (3x3), both images per thread, fp16 out + stats1 ----------------
__global__ __launch_bounds__(256) void k_conv1(const float* __restrict__ x,
                                               const float* __restrict__ w1) {
    __shared__ float s_w[144];
    __shared__ float s_in[512];
    __shared__ float s_red[256];
    int t = threadIdx.x;
    if (t < 144) s_w[t] = w1[t];
    int c = t & 15, chunk = t >> 4;   // 16 chunks over 196 positions
    __syncthreads();
    const float* wc = &s_w[c * 9];
    float w00 = wc[0], w01 = wc[1], w02 = wc[2];
    float w10 = wc[3], w11 = wc[4], w12 = wc[5];
    float w20 = wc[6], w21 = wc[7], w22 = wc[8];
    float ls = 0.f, lsq = 0.f;
    int pair0 = blockIdx.x * 4;

    for (int pp = 0; pp < 4; pp++) {
        int pair = pair0 + pp;
        __syncthreads();
        const float* xp = x + (size_t)pair * 512;
        s_in[t] = xp[t];
        s_in[256 + t] = xp[256 + t];
        __syncthreads();
        __half2* dst = &g_h1[(size_t)pair * 3136];
        for (int p = chunk; p < 196; p += 16) {
            int y = p / 14, xx = p - y * 14;
            const float* r0 = &s_in[y * 16 + xx];
            const float* r1 = r0 + 256;
            float a0 = r0[0]  * w00 + r0[1]  * w01 + r0[2]  * w02
                     + r0[16] * w10 + r0[17] * w11 + r0[18] * w12
                     + r0[32] * w20 + r0[33] * w21 + r0[34] * w22;
            float a1 = r1[0]  * w00 + r1[1]  * w01 + r1[2]  * w02
                     + r1[16] * w10 + r1[17] * w11 + r1[18] * w12
                     + r1[32] * w20 + r1[33] * w21 + r1[34] * w22;
            __half2 hv = __floats2half2_rn(a0, a1);
            __stwt(&dst[p * 16 + c], hv);
            float b0 = __half2float(__low2half(hv));
            float b1 = __half2float(__high2half(hv));
            ls += b0 + b1; lsq += b0 * b0 + b1 * b1;
        }
    }
    __syncthreads();
    s_red[t] = ls;
    __syncthreads();
    if (t < 16) { float s = 0.f; for (int j = 0; j < 16; j++) s += s_red[t + 16 * j];
                  atomicAdd(&g_s1[t], s); }
    __syncthreads();
    s_red[t] = lsq;
    __syncthreads();
    if (t < 16) { float s = 0.f; for (int j = 0; j < 16; j++) s += s_red[t + 16 * j];
                  atomicAdd(&g_s1[16 + t], s); }
}

// ---------------- BN params for layers 1,2 ----------------
__global__ void k_finalize(int which, const float* __restrict__ gamma,
                           const float* __restrict__ beta) {
    int C     = (which == 0) ? 16 : 32;
    float* s  = (which == 0) ? g_s1 : g_s2;
    float* bn = (which == 0) ? g_bn1 : g_bn2;
    float n   = (which == 0) ? (16384.f * 196.f) : (16384.f * 169.f);
    int t = threadIdx.x;
    if (t < C) {
        float mean = s[t] / n;
        float var  = s[C + t] / n - mean * mean;
        float sc   = gamma[t] * rsqrtf(var + 1e-5f);
        bn[t] = sc;
        bn[C + t] = beta[t] - mean * sc;
    }
}

// ---------------- bn1+relu -> conv2 (2x2) via f32x2; fp16 out + stats2 (R9 version) ----------------
__global__ __launch_bounds__(256) void k_conv2(const float* __restrict__ w2) {
    __shared__ __align__(16) float s_a[196 * 32];   // [196][16ch][2img]
    __shared__ float s_red[256];
    __shared__ float s_bn[32];
    int t = threadIdx.x;
    if (t < 32) s_bn[t] = g_bn1[t];
    int c2 = t & 31, chunk = t >> 5;   // 8 chunks over 169 positions
    ull wp[64];
    {
        const float4* wsrc = reinterpret_cast<const float4*>(w2) + c2 * 16;
#pragma unroll
        for (int i = 0; i < 16; i++) {
            float4 v = wsrc[i];
            wp[4 * i]     = pk2(v.x, v.x);
            wp[4 * i + 1] = pk2(v.y, v.y);
            wp[4 * i + 2] = pk2(v.z, v.z);
            wp[4 * i + 3] = pk2(v.w, v.w);
        }
    }
    float ls = 0.f, lsq = 0.f;
    int pair0 = blockIdx.x * 4;

    for (int pp = 0; pp < 4; pp++) {
        int pair = pair0 + pp;
        __syncthreads();
        const __half2* src = &g_h1[(size_t)pair * 3136];
        for (int i = t; i < 3136; i += 256) {
            float2 v = __half22float2(src[i]);
            int c = i & 15;
            float sc = s_bn[c], bi = s_bn[16 + c];
            s_a[2 * i]     = fmaxf(fmaf(v.x, sc, bi), 0.f);
            s_a[2 * i + 1] = fmaxf(fmaf(v.y, sc, bi), 0.f);
        }
        __syncthreads();
        __half2* dst = &g_h2[(size_t)pair * 5408];
        const ulonglong2* ap2 = reinterpret_cast<const ulonglong2*>(s_a);
        for (int p = chunk; p < 169; p += 8) {
            int y = p / 13, xx = p - y * 13;
            int r0 = (y * 14 + xx) * 8;
            ull acc0 = pk2(0.f, 0.f), acc1 = acc0, acc2 = acc0, acc3 = acc0;
#pragma unroll
            for (int h = 0; h < 8; h++) {
                ulonglong2 A00 = ap2[r0 + h];
                ulonglong2 A01 = ap2[r0 + 8 + h];
                ulonglong2 A10 = ap2[r0 + 112 + h];
                ulonglong2 A11 = ap2[r0 + 120 + h];
                FMA2(acc0, A00.x, wp[8 * h]);     FMA2(acc1, A00.y, wp[8 * h + 4]);
                FMA2(acc2, A01.x, wp[8 * h + 1]); FMA2(acc3, A01.y, wp[8 * h + 5]);
                FMA2(acc0, A10.x, wp[8 * h + 2]); FMA2(acc1, A10.y, wp[8 * h + 6]);
                FMA2(acc2, A11.x, wp[8 * h + 3]); FMA2(acc3, A11.y, wp[8 * h + 7]);
            }
            float xa, xb, xc, xd, ya, yb, yc, yd;
            upk2(acc0, xa, ya); upk2(acc1, xb, yb);
            upk2(acc2, xc, yc); upk2(acc3, xd, yd);
            float a0 = (xa + xb) + (xc + xd);
            float a1 = (ya + yb) + (yc + yd);
            __half2 hv = __floats2half2_rn(a0, a1);
            dst[p * 32 + c2] = hv;
            float b0 = __half2float(__low2half(hv));
            float b1 = __half2float(__high2half(hv));
            ls += b0 + b1; lsq += b0 * b0 + b1 * b1;
        }
    }
    __syncthreads();
    s_red[t] = ls;
    __syncthreads();
    if (t < 32) { float s = 0.f; for (int j = 0; j < 8; j++) s += s_red[t + 32 * j];
                  atomicAdd(&g_s2[t], s); }
    __syncthreads();
    s_red[t] = lsq;
    __syncthreads();
    if (t < 32) { float s = 0.f; for (int j = 0; j < 8; j++) s += s_red[t + 32 * j];
                  atomicAdd(&g_s2[32 + t], s); }
}

// ---------------- bn2+relu -> Gram of a2; ALSO writes a2 back to g_h2 in place ----------------
__global__ __launch_bounds__(256) void k_gram() {
    __shared__ __align__(16) float s_a[169 * 64];   // [p][32ch][2img]
    __shared__ float s_bn[64];
    int t = threadIdx.x;
    if (t < 64) s_bn[t] = g_bn2[t];
    int slot = t >> 6;
    int idx = t & 63;
    int r4 = (idx >> 3) * 4;
    int c4 = (idx & 7) * 4;
    ull acc[4][4];
#pragma unroll
    for (int i = 0; i < 4; i++)
#pragma unroll
        for (int j = 0; j < 4; j++) acc[i][j] = pk2(0.f, 0.f);
    ull sA[4] = {pk2(0.f,0.f), pk2(0.f,0.f), pk2(0.f,0.f), pk2(0.f,0.f)};
    const ull one2 = pk2(1.f, 1.f);
    int pair0 = blockIdx.x * 4;

    for (int pp = 0; pp < 4; pp++) {
        __syncthreads();
        __half2* src = &g_h2[(size_t)(pair0 + pp) * 5408];
        for (int i = t; i < 169 * 32; i += 256) {
            float2 v = __half22float2(src[i]);
            int c = i & 31;
            float sc = s_bn[c], bi = s_bn[32 + c];
            float ax = fmaxf(fmaf(v.x, sc, bi), 0.f);
            float ay = fmaxf(fmaf(v.y, sc, bi), 0.f);
            __half2 hv = __floats2half2_rn(ax, ay);
            src[i] = hv;                         // a2 written back (in place)
            float2 rb = __half22float2(hv);      // stats on rounded values
            s_a[2 * i]     = rb.x;
            s_a[2 * i + 1] = rb.y;
        }
        __syncthreads();
        const ulonglong2* ap = reinterpret_cast<const ulonglong2*>(s_a);
        for (int p = slot; p < 169; p += 4) {
            ulonglong2 ra = ap[p * 16 + (r4 >> 1)];
            ulonglong2 rb = ap[p * 16 + (r4 >> 1) + 1];
            ulonglong2 ca = ap[p * 16 + (c4 >> 1)];
            ulonglong2 cb = ap[p * 16 + (c4 >> 1) + 1];
            ull rr[4] = {ra.x, ra.y, rb.x, rb.y};
            ull cc[4] = {ca.x, ca.y, cb.x, cb.y};
#pragma unroll
            for (int i = 0; i < 4; i++)
#pragma unroll
                for (int j = 0; j < 4; j++) FMA2(acc[i][j], rr[i], cc[j]);
            if (c4 == 0) {
#pragma unroll
                for (int i = 0; i < 4; i++) FMA2(sA[i], rr[i], one2);
            }
        }
    }
    float lo, hi;
#pragma unroll
    for (int i = 0; i < 4; i++)
#pragma unroll
        for (int j = 0; j < 4; j++) {
            upk2(acc[i][j], lo, hi);
            atomicAdd(&g_gram[(r4 + i) * 32 + c4 + j], lo + hi);
        }
    if (c4 == 0) {
#pragma unroll
        for (int i = 0; i < 4; i++) { upk2(sA[i], lo, hi); atomicAdd(&g_sumA[r4 + i], lo + hi); }
    }
}

// ---------------- bn3 params from Gram ----------------
__global__ void k_fin3(const float* __restrict__ w3, const float* __restrict__ gamma,
                       const float* __restrict__ beta) {
    __shared__ float s_m[1024];
    __shared__ float s_A[32];
    __shared__ float s_w[64 * 33];
    int t = threadIdx.x;    // 64 threads
    for (int i = t; i < 1024; i += 64) s_m[i] = g_gram[i];
    if (t < 32) s_A[t] = g_sumA[t];
    for (int kk = 0; kk < 32; kk++) s_w[t * 33 + kk] = w3[t * 32 + kk];
    __syncthreads();
    float S1 = 0.f, S2 = 0.f;
    for (int k = 0; k < 32; k++) {
        float wk = s_w[t * 33 + k];
        S1 += wk * s_A[k];
        float inner = 0.f;
        for (int kp = 0; kp < 32; kp++) inner += s_w[t * 33 + kp] * s_m[k * 32 + kp];
        S2 += wk * inner;
    }
    float n = 16384.f * 169.f;
    float mean = S1 / n;
    float var  = S2 / n - mean * mean;
    float sc   = gamma[t] * rsqrtf(var + 1e-5f);
    g_bn3[t] = sc;
    g_bn3[64 + t] = beta[t] - mean * sc;
}

// ---------------- conv3 + bn3 + relu + fc PARTIAL over a c3-range ----------------
// grid (256, 4): blockIdx.x = pair-block (32 pairs), blockIdx.y = c3-range (16 c3).
// Each CTA reads a 130KB fc_w slice (L1-resident) for 32 pairs; a2 rows come
// straight from g_h2 (coalesced 128B/lane). Partials -> g_part[range].
#define FIN_THREADS 192
#define FB_PAIRS 32
__global__ __launch_bounds__(FIN_THREADS) void k_final(const float* __restrict__ w3) {
    __shared__ float s_w3d[1024];    // [c3l(16)][k(32)][2] duplicated
    __shared__ float s_sc[16], s_bi[16];
    __shared__ float s_red[6 * 20];
    int t = threadIdx.x;
    int r = blockIdx.y;
    int c3base = r * 16;
    for (int i = t; i < 1024; i += FIN_THREADS) {
        int c3l = i >> 6, kd = i & 63;
        s_w3d[i] = w3[(c3base + c3l) * 32 + (kd >> 1)];
    }
    if (t < 16) { s_sc[t] = g_bn3[c3base + t]; s_bi[t] = g_bn3[64 + c3base + t]; }
    __syncthreads();

    int lane = t & 31, wid = t >> 5;
    int p = wid * 32 + lane;
    int pc = p < 169 ? p : 168;
    bool valid = p < 169;
    const float4* fwp = reinterpret_cast<const float4*>(g_fcwp);

    for (int q = 0; q < FB_PAIRS; q++) {
        size_t pair = (size_t)blockIdx.x * FB_PAIRS + q;
        const uint4* row = reinterpret_cast<const uint4*>(&g_h2[pair * 5408 + pc * 32]);
        // load a2 row (32 half2 = 128B) and unpack to f32x2
        ull a2r[32];
#pragma unroll
        for (int i = 0; i < 8; i++) {
            uint4 u = row[i];
            float2 f0 = __half22float2(*reinterpret_cast<const __half2*>(&u.x));
            float2 f1 = __half22float2(*reinterpret_cast<const __half2*>(&u.y));
            float2 f2 = __half22float2(*reinterpret_cast<const __half2*>(&u.z));
            float2 f3 = __half22float2(*reinterpret_cast<const __half2*>(&u.w));
            a2r[4 * i]     = pk2(f0.x, f0.y);
            a2r[4 * i + 1] = pk2(f1.x, f1.y);
            a2r[4 * i + 2] = pk2(f2.x, f2.y);
            a2r[4 * i + 3] = pk2(f3.x, f3.y);
        }
        float o0[10], o1[10];
#pragma unroll
        for (int j = 0; j < 10; j++) { o0[j] = 0.f; o1[j] = 0.f; }

#pragma unroll 4
        for (int c3l = 0; c3l < 16; c3l++) {
            const ulonglong2* wr = reinterpret_cast<const ulonglong2*>(&s_w3d[c3l * 64]);
            ull acc0 = pk2(0.f, 0.f), acc1 = acc0, acc2 = acc0, acc3 = acc0;
#pragma unroll
            for (int i = 0; i < 8; i++) {
                ulonglong2 va = wr[2 * i];
                ulonglong2 vb = wr[2 * i + 1];
                FMA2(acc0, a2r[4 * i],     va.x);
                FMA2(acc1, a2r[4 * i + 1], va.y);
                FMA2(acc2, a2r[4 * i + 2], vb.x);
                FMA2(acc3, a2r[4 * i + 3], vb.y);
            }
            float e0, e1, e2, e3, f0, f1, f2, f3;
            upk2(acc0, e0, f0); upk2(acc1, e1, f1);
            upk2(acc2, e2, f2); upk2(acc3, e3, f3);
            float sc = s_sc[c3l], bi = s_bi[c3l];
            float v0 = fmaxf(fmaf((e0 + e1) + (e2 + e3), sc, bi), 0.f);
            float v1 = fmaxf(fmaf((f0 + f1) + (f2 + f3), sc, bi), 0.f);
            int base = ((c3base + c3l) * 169 + pc) * 3;
            float4 w0 = fwp[base], w1 = fwp[base + 1], w2 = fwp[base + 2];
            o0[0] += v0 * w0.x; o1[0] += v1 * w0.x;
            o0[1] += v0 * w0.y; o1[1] += v1 * w0.y;
            o0[2] += v0 * w0.z; o1[2] += v1 * w0.z;
            o0[3] += v0 * w0.w; o1[3] += v1 * w0.w;
            o0[4] += v0 * w1.x; o1[4] += v1 * w1.x;
            o0[5] += v0 * w1.y; o1[5] += v1 * w1.y;
            o0[6] += v0 * w1.z; o1[6] += v1 * w1.z;
            o0[7] += v0 * w1.w; o1[7] += v1 * w1.w;
            o0[8] += v0 * w2.x; o1[8] += v1 * w2.x;
            o0[9] += v0 * w2.y; o1[9] += v1 * w2.y;
        }
#pragma unroll
        for (int j = 0; j < 10; j++) {
            if (!valid) { o0[j] = 0.f; o1[j] = 0.f; }
#pragma unroll
            for (int off = 16; off > 0; off >>= 1) {
                o0[j] += __shfl_xor_sync(0xffffffffu, o0[j], off);
                o1[j] += __shfl_xor_sync(0xffffffffu, o1[j], off);
            }
        }
        if (lane == 0) {
#pragma unroll
            for (int j = 0; j < 10; j++) {
                s_red[wid * 20 + j]      = o0[j];
                s_red[wid * 20 + 10 + j] = o1[j];
            }
        }
        __syncthreads();
        if (t < 20) {
            float s = s_red[t] + s_red[20 + t] + s_red[40 + t]
                    + s_red[60 + t] + s_red[80 + t] + s_red[100 + t];
            int im = t / 10, j = t - im * 10;
            g_part[((size_t)r * 16384 + pair * 2 + im) * 10 + j] = s;
        }
        __syncthreads();
    }
}

// ---------------- sum partials + bias ----------------
__global__ void k_fcsum(const float* __restrict__ fc_b, float* __restrict__ out) {
    int i = blockIdx.x * 256 + threadIdx.x;
    if (i >= 163840) return;
    int j = i % 10;
    out[i] = ((g_part[i] + g_part[163840 + i])
            + (g_part[327680 + i] + g_part[491520 + i])) + fc_b[j];
}

// ---------------- launch ----------------
extern "C" void kernel_launch(void* const* d_in, const int* in_sizes, int n_in,
                              void* d_out, int out_size) {
    const float* x    = (const float*)d_in[0];
    const float* w1   = (const float*)d_in[1];
    const float* w2   = (const float*)d_in[2];
    const float* w3   = (const float*)d_in[3];
    const float* g1   = (const float*)d_in[4];
    const float* b1   = (const float*)d_in[5];
    const float* g2   = (const float*)d_in[6];
    const float* b2   = (const float*)d_in[7];
    const float* g3   = (const float*)d_in[8];
    const float* b3   = (const float*)d_in[9];
    const float* fc_w = (const float*)d_in[10];
    const float* fc_b = (const float*)d_in[11];
    float* out = (float*)d_out;

    k_zero<<<1, 1024>>>();
    k_packfc<<<43, 256>>>(fc_w);
    k_conv1<<<2048, 256>>>(x, w1);
    k_finalize<<<1, 64>>>(0, g1, b1);
    k_conv2<<<2048, 256>>>(w2);
    k_finalize<<<1, 64>>>(1, g2, b2);
    k_gram<<<2048, 256>>>();
    k_fin3<<<1, 64>>>(w3, g3, b3);
    dim3 fgrid(NPAIR / FB_PAIRS, 4);   // (256, 4)
    k_final<<<fgrid, FIN_THREADS>>>(w3);
    k_fcsum<<<640, 256>>>(fc_b, out);
}

// round 16
// speedup vs baseline: 1.4144x; 1.3019x over previous
#include <cuda_runtime.h>
#include <cuda_fp16.h>
#include <cstdint>

#define NPAIR 8192              // 16384 images as 8192 pairs

// Layouts:
//  g_h1: [pair][img][196][16] fp16 (102 MB)  de-interleaved
//  g_h2: [pair][169][32] half2 (177 MB)      (img0,img1) interleaved
__device__ __half  g_h1[(size_t)NPAIR * 2 * 196 * 16];
__device__ __half2 g_h2[(size_t)NPAIR * 169 * 32];
__device__ float g_fcwp[64 * 169 * 12];   // fc_w packed [c3][p][j(10)+pad2]
__device__ float g_s1[32];      // sum[16], sumsq[16]
__device__ float g_s2[64];      // sum[32], sumsq[32]
__device__ float g_gram[1024];  // M[32][32]
__device__ float g_sumA[32];    // A[k]
__device__ float g_bn1[32];
__device__ float g_bn2[64];
__device__ float g_bn3[128];

// ---------------- helpers ----------------
typedef unsigned long long ull;
__device__ __forceinline__ ull pk2(float a, float b) {
    ull r; asm("mov.b64 %0, {%1, %2};" : "=l"(r) : "f"(a), "f"(b)); return r;
}
__device__ __forceinline__ void upk2(ull v, float& a, float& b) {
    asm("mov.b64 {%0, %1}, %2;" : "=f"(a), "=f"(b) : "l"(v));
}
#define FMA2(d, a, b) asm("fma.rn.f32x2 %0, %1, %2, %0;" : "+l"(d) : "l"(a), "l"(b))

__device__ __forceinline__ uint32_t h2u(__half2 h) {
    __half2_raw r = *reinterpret_cast<__half2_raw*>(&h);
    return (uint32_t)r.x | ((uint32_t)r.y << 16);
}
__device__ __forceinline__ uint32_t smem_u32(const void* p) {
    uint32_t a;
    asm("{ .reg .u64 t; cvta.to.shared.u64 t, %1; cvt.u32.u64 %0, t; }" : "=r"(a) : "l"(p));
    return a;
}

// mma.sync m16n8k16 fp16 -> f32 (sm_80+ PTX; HMMA on sm_103)
__device__ __forceinline__ void mma16816(float* c, const uint32_t* a, const uint32_t* b) {
    asm volatile(
        "mma.sync.aligned.m16n8k16.row.col.f32.f16.f16.f32 "
        "{%0,%1,%2,%3}, {%4,%5,%6,%7}, {%8,%9}, {%0,%1,%2,%3};"
        : "+f"(c[0]), "+f"(c[1]), "+f"(c[2]), "+f"(c[3])
        : "r"(a[0]), "r"(a[1]), "r"(a[2]), "r"(a[3]), "r"(b[0]), "r"(b[1]));
}
#define LDSM_X4(a0, a1, a2, a3, addr) \
    asm volatile("ldmatrix.sync.aligned.m8n8.x4.shared.b16 {%0,%1,%2,%3}, [%4];" \
        : "=r"(a0), "=r"(a1), "=r"(a2), "=r"(a3) : "r"(addr))

// ---------------- zero accumulators ----------------
__global__ void k_zero() {
    int t = threadIdx.x;
    g_gram[t] = 0.f;
    if (t < 32) { g_s1[t] = 0.f; g_sumA[t] = 0.f; }
    if (t < 64) g_s2[t] = 0.f;
}

// ---------------- pack fc_w -> [c3][p][12] ----------------
__global__ void k_packfc(const float* __restrict__ fc_w) {
    int i = blockIdx.x * 256 + threadIdx.x;
    if (i >= 10816) return;
#pragma unroll
    for (int j = 0; j < 10; j++) g_fcwp[i * 12 + j] = fc_w[(size_t)j * 10816 + i];
    g_fcwp[i * 12 + 10] = 0.f;
    g_fcwp[i * 12 + 11] = 0.f;
}

// ---------------- conv1 (3x3); h1 de-interleaved fp16 + stats1 ----------------
__global__ __launch_bounds__(256) void k_conv1(const float* __restrict__ x,
                                               const float* __restrict__ w1) {
    __shared__ float s_w[144];
    __shared__ float s_in[512];
    __shared__ float s_red[256];
    int t = threadIdx.x;
    if (t < 144) s_w[t] = w1[t];
    int c = t & 15, chunk = t >> 4;
    __syncthreads();
    const float* wc = &s_w[c * 9];
    float w00 = wc[0], w01 = wc[1], w02 = wc[2];
    float w10 = wc[3], w11 = wc[4], w12 = wc[5];
    float w20 = wc[6], w21 = wc[7], w22 = wc[8];
    float ls = 0.f, lsq = 0.f;
    int pair0 = blockIdx.x * 4;

    for (int pp = 0; pp < 4; pp++) {
        int pair = pair0 + pp;
        __syncthreads();
        const float* xp = x + (size_t)pair * 512;
        s_in[t] = xp[t];
        s_in[256 + t] = xp[256 + t];
        __syncthreads();
        __half* dst = &g_h1[(size_t)pair * 6272];
        for (int p = chunk; p < 196; p += 16) {
            int y = p / 14, xx = p - y * 14;
            const float* r0 = &s_in[y * 16 + xx];
            const float* r1 = r0 + 256;
            float a0 = r0[0]  * w00 + r0[1]  * w01 + r0[2]  * w02
                     + r0[16] * w10 + r0[17] * w11 + r0[18] * w12
                     + r0[32] * w20 + r0[33] * w21 + r0[34] * w22;
            float a1 = r1[0]  * w00 + r1[1]  * w01 + r1[2]  * w02
                     + r1[16] * w10 + r1[17] * w11 + r1[18] * w12
                     + r1[32] * w20 + r1[33] * w21 + r1[34] * w22;
            __half h0 = __float2half_rn(a0), h1v = __float2half_rn(a1);
            dst[p * 16 + c] = h0;
            dst[3136 + p * 16 + c] = h1v;
            float b0 = __half2float(h0), b1 = __half2float(h1v);
            ls += b0 + b1; lsq += b0 * b0 + b1 * b1;
        }
    }
    __syncthreads();
    s_red[t] = ls;
    __syncthreads();
    if (t < 16) { float s = 0.f; for (int j = 0; j < 16; j++) s += s_red[t + 16 * j];
                  atomicAdd(&g_s1[t], s); }
    __syncthreads();
    s_red[t] = lsq;
    __syncthreads();
    if (t < 16) { float s = 0.f; for (int j = 0; j < 16; j++) s += s_red[t + 16 * j];
                  atomicAdd(&g_s1[16 + t], s); }
}

// ---------------- BN params for layers 1,2 ----------------
__global__ void k_finalize(int which, const float* __restrict__ gamma,
                           const float* __restrict__ beta) {
    int C     = (which == 0) ? 16 : 32;
    float* s  = (which == 0) ? g_s1 : g_s2;
    float* bn = (which == 0) ? g_bn1 : g_bn2;
    float n   = (which == 0) ? (16384.f * 196.f) : (16384.f * 169.f);
    int t = threadIdx.x;
    if (t < C) {
        float mean = s[t] / n;
        float var  = s[C + t] / n - mean * mean;
        float sc   = gamma[t] * rsqrtf(var + 1e-5f);
        bn[t] = sc;
        bn[C + t] = beta[t] - mean * sc;
    }
}

// ---------------- conv2 via mma.sync (HMMA) im2col GEMM ----------------
// Per pair: A [img][176 rows x 64 K] fp16, 144B padded rows (conflict-free LDSM);
// B = w2 fragments in registers; 22 M-tiles x 4 N-tiles x 4 K-steps of m16n8k16;
// f32 accums -> fp16 outbuf -> pack (img0,img1) half2 into g_h2 + stats.
// Dyn smem: A 2x25344 + out 2x11264 = 73216 B.
__global__ __launch_bounds__(256) void k_conv2(const float* __restrict__ w2) {
    extern __shared__ __align__(16) char dsm[];
    __shared__ float s_bn[32];
    __shared__ float s_red[256];
    const uint32_t A_BYTES = 25344u;     // 176*144
    const uint32_t OUT_OFF = 50688u;     // 2*A_BYTES
    const uint32_t OUT_IMG = 11264u;     // 176*32*2
    int t = threadIdx.x, wid = t >> 5, lane = t & 31;
    if (t < 32) s_bn[t] = g_bn1[t];

    // ---- build B fragments from w2 (staged via outbuf scratch) ----
    uint32_t bf[4][4][2];
    {
        float* s_w2f = reinterpret_cast<float*>(dsm + OUT_OFF);
        for (int i = t; i < 2048; i += 256) s_w2f[i] = w2[i];
        __syncthreads();
        int n_lo = lane >> 2, c1b = (lane & 3) * 2;
#pragma unroll
        for (int ks = 0; ks < 4; ks++)
#pragma unroll
            for (int nt = 0; nt < 4; nt++) {
                int n = nt * 8 + n_lo;
                const float* wp = &s_w2f[n * 64 + ks];
                bf[ks][nt][0] = h2u(__floats2half2_rn(wp[c1b * 4],       wp[(c1b + 1) * 4]));
                bf[ks][nt][1] = h2u(__floats2half2_rn(wp[(c1b + 8) * 4], wp[(c1b + 9) * 4]));
            }
        __syncthreads();
    }

    uint32_t abase_s = smem_u32(dsm);
    float ls = 0.f, lsq = 0.f;
    int pair0 = blockIdx.x * 4;

    for (int pp = 0; pp < 4; pp++) {
        size_t pair = pair0 + pp;
        __syncthreads();
        // ---- stage im2col A tiles (both images) ----
        for (int i = t; i < 392; i += 256) {
            int img = i >= 196, cell = i - img * 196;
            int y = cell / 14, xx = cell - y * 14;
            const uint4* sp = reinterpret_cast<const uint4*>(
                &g_h1[pair * 6272 + img * 3136 + cell * 16]);
            uint4 u0 = sp[0], u1 = sp[1];
            uint32_t r[8];
            const __half2* h0 = reinterpret_cast<const __half2*>(&u0);
            const __half2* h1 = reinterpret_cast<const __half2*>(&u1);
#pragma unroll
            for (int j = 0; j < 4; j++) {
                float2 v = __half22float2(h0[j]);
                int c = 2 * j;
                float ax = fmaxf(fmaf(v.x, s_bn[c],     s_bn[16 + c]),     0.f);
                float ay = fmaxf(fmaf(v.y, s_bn[c + 1], s_bn[16 + c + 1]), 0.f);
                r[j] = h2u(__floats2half2_rn(ax, ay));
            }
#pragma unroll
            for (int j = 0; j < 4; j++) {
                float2 v = __half22float2(h1[j]);
                int c = 8 + 2 * j;
                float ax = fmaxf(fmaf(v.x, s_bn[c],     s_bn[16 + c]),     0.f);
                float ay = fmaxf(fmaf(v.y, s_bn[c + 1], s_bn[16 + c + 1]), 0.f);
                r[4 + j] = h2u(__floats2half2_rn(ax, ay));
            }
            uint4 lo = make_uint4(r[0], r[1], r[2], r[3]);
            uint4 hi = make_uint4(r[4], r[5], r[6], r[7]);
            char* aimg = dsm + img * A_BYTES;
#pragma unroll
            for (int dy = 0; dy < 2; dy++) {
                int py = y - dy;
                if (py < 0 || py > 12) continue;
#pragma unroll
                for (int dx = 0; dx < 2; dx++) {
                    int px = xx - dx;
                    if (px < 0 || px > 12) continue;
                    int row = py * 13 + px;
                    uint32_t off = row * 144 + (dy * 2 + dx) * 32;
                    *reinterpret_cast<uint4*>(aimg + off) = lo;
                    *reinterpret_cast<uint4*>(aimg + off + 16) = hi;
                }
            }
        }
        __syncthreads();
        // ---- mma: 22 tile-images over 8 warps ----
        for (int tile = wid; tile < 22; tile += 8) {
            int img = tile / 11, mt = tile - img * 11;
            uint32_t arow = abase_s + img * A_BYTES
                          + (mt * 16 + (lane & 15)) * 144 + ((lane >> 4) ? 16 : 0);
            float C[4][4];
#pragma unroll
            for (int nt = 0; nt < 4; nt++)
#pragma unroll
                for (int j = 0; j < 4; j++) C[nt][j] = 0.f;
#pragma unroll
            for (int ks = 0; ks < 4; ks++) {
                uint32_t a[4];
                LDSM_X4(a[0], a[1], a[2], a[3], arow + ks * 32);
#pragma unroll
                for (int nt = 0; nt < 4; nt++)
                    mma16816(C[nt], a, bf[ks][nt]);
            }
            // epilogue to fp16 outbuf
            char* outp = dsm + OUT_OFF + img * OUT_IMG;
            int row = mt * 16 + (lane >> 2);
#pragma unroll
            for (int nt = 0; nt < 4; nt++) {
                int col = nt * 8 + (lane & 3) * 2;
                *reinterpret_cast<uint32_t*>(outp + (row * 32 + col) * 2) =
                    h2u(__floats2half2_rn(C[nt][0], C[nt][1]));
                *reinterpret_cast<uint32_t*>(outp + ((row + 8) * 32 + col) * 2) =
                    h2u(__floats2half2_rn(C[nt][2], C[nt][3]));
            }
        }
        __syncthreads();
        // ---- pack (img0,img1) half2 -> g_h2 + stats ----
        const __half* outh = reinterpret_cast<const __half*>(dsm + OUT_OFF);
        __half2* dst = &g_h2[pair * 5408];
        for (int i = t; i < 5408; i += 256) {
            __half h0 = outh[i];
            __half h1v = outh[5632 + i];
            dst[i] = __halves2half2(h0, h1v);
            float f0 = __half2float(h0), f1 = __half2float(h1v);
            ls += f0 + f1; lsq += f0 * f0 + f1 * f1;
        }
    }
    __syncthreads();
    s_red[t] = ls;
    __syncthreads();
    if (t < 32) { float s = 0.f; for (int j = 0; j < 8; j++) s += s_red[t + 32 * j];
                  atomicAdd(&g_s2[t], s); }
    __syncthreads();
    s_red[t] = lsq;
    __syncthreads();
    if (t < 32) { float s = 0.f; for (int j = 0; j < 8; j++) s += s_red[t + 32 * j];
                  atomicAdd(&g_s2[32 + t], s); }
}

// ---------------- bn2+relu -> Gram of a2, 4x4 register tiles (R9) ----------------
__global__ __launch_bounds__(256) void k_gram() {
    __shared__ __align__(16) float s_a[169 * 64];
    __shared__ float s_bn[64];
    int t = threadIdx.x;
    if (t < 64) s_bn[t] = g_bn2[t];
    int slot = t >> 6;
    int idx = t & 63;
    int r4 = (idx >> 3) * 4;
    int c4 = (idx & 7) * 4;
    ull acc[4][4];
#pragma unroll
    for (int i = 0; i < 4; i++)
#pragma unroll
        for (int j = 0; j < 4; j++) acc[i][j] = pk2(0.f, 0.f);
    ull sA[4] = {pk2(0.f,0.f), pk2(0.f,0.f), pk2(0.f,0.f), pk2(0.f,0.f)};
    const ull one2 = pk2(1.f, 1.f);
    int pair0 = blockIdx.x * 4;

    for (int pp = 0; pp < 4; pp++) {
        __syncthreads();
        const __half2* src = &g_h2[(size_t)(pair0 + pp) * 5408];
        for (int i = t; i < 169 * 32; i += 256) {
            float2 v = __half22float2(src[i]);
            int c = i & 31;
            float sc = s_bn[c], bi = s_bn[32 + c];
            s_a[2 * i]     = fmaxf(fmaf(v.x, sc, bi), 0.f);
            s_a[2 * i + 1] = fmaxf(fmaf(v.y, sc, bi), 0.f);
        }
        __syncthreads();
        const ulonglong2* ap = reinterpret_cast<const ulonglong2*>(s_a);
        for (int p = slot; p < 169; p += 4) {
            ulonglong2 ra = ap[p * 16 + (r4 >> 1)];
            ulonglong2 rb = ap[p * 16 + (r4 >> 1) + 1];
            ulonglong2 ca = ap[p * 16 + (c4 >> 1)];
            ulonglong2 cb = ap[p * 16 + (c4 >> 1) + 1];
            ull rr[4] = {ra.x, ra.y, rb.x, rb.y};
            ull cc[4] = {ca.x, ca.y, cb.x, cb.y};
#pragma unroll
            for (int i = 0; i < 4; i++)
#pragma unroll
                for (int j = 0; j < 4; j++) FMA2(acc[i][j], rr[i], cc[j]);
            if (c4 == 0) {
#pragma unroll
                for (int i = 0; i < 4; i++) FMA2(sA[i], rr[i], one2);
            }
        }
    }
    float lo, hi;
#pragma unroll
    for (int i = 0; i < 4; i++)
#pragma unroll
        for (int j = 0; j < 4; j++) {
            upk2(acc[i][j], lo, hi);
            atomicAdd(&g_gram[(r4 + i) * 32 + c4 + j], lo + hi);
        }
    if (c4 == 0) {
#pragma unroll
        for (int i = 0; i < 4; i++) { upk2(sA[i], lo, hi); atomicAdd(&g_sumA[r4 + i], lo + hi); }
    }
}

// ---------------- bn3 params from Gram (R9) ----------------
__global__ void k_fin3(const float* __restrict__ w3, const float* __restrict__ gamma,
                       const float* __restrict__ beta) {
    __shared__ float s_m[1024];
    __shared__ float s_A[32];
    __shared__ float s_w[64 * 33];
    int t = threadIdx.x;    // 64 threads
    for (int i = t; i < 1024; i += 64) s_m[i] = g_gram[i];
    if (t < 32) s_A[t] = g_sumA[t];
    for (int kk = 0; kk < 32; kk++) s_w[t * 33 + kk] = w3[t * 32 + kk];
    __syncthreads();
    float S1 = 0.f, S2 = 0.f;
    for (int k = 0; k < 32; k++) {
        float wk = s_w[t * 33 + k];
        S1 += wk * s_A[k];
        float inner = 0.f;
        for (int kp = 0; kp < 32; kp++) inner += s_w[t * 33 + kp] * s_m[k * 32 + kp];
        S2 += wk * inner;
    }
    float n = 16384.f * 169.f;
    float mean = S1 / n;
    float var  = S2 / n - mean * mean;
    float sc   = gamma[t] * rsqrtf(var + 1e-5f);
    g_bn3[t] = sc;
    g_bn3[64 + t] = beta[t] - mean * sc;
}

// ---------------- bn2+relu -> conv3 (f32x2) -> bn3+relu -> fc (R9) ----------------
#define FIN_THREADS 192
__global__ __launch_bounds__(FIN_THREADS) void k_final(const float* __restrict__ w3,
                                                       const float* __restrict__ fc_b,
                                                       float* __restrict__ out) {
    extern __shared__ __align__(16) float sm[];
    float* s_a2 = sm;                 // [169][68] padded rows
    float* s_wd = sm + 169 * 68;      // w3 duplicated: [c3][k][2]
    __shared__ float s_bn2[64];
    __shared__ float s_bn3[128];
    __shared__ float s_out[20];
    int t = threadIdx.x;
    if (t < 64)  s_bn2[t] = g_bn2[t];
    if (t < 128) s_bn3[t] = g_bn3[t];
    if (t < 20)  s_out[t] = 0.f;
    for (int i = t; i < 2048; i += FIN_THREADS) {
        float w = w3[i];
        s_wd[2 * i] = w; s_wd[2 * i + 1] = w;
    }
    size_t pair = blockIdx.x;
    const __half2* src = &g_h2[pair * 5408];
    __syncthreads();
    for (int i = t; i < 169 * 32; i += FIN_THREADS) {
        float2 v = __half22float2(src[i]);
        int c = i & 31, p = i >> 5;
        float sc = s_bn2[c], bi = s_bn2[32 + c];
        float2 o;
        o.x = fmaxf(fmaf(v.x, sc, bi), 0.f);
        o.y = fmaxf(fmaf(v.y, sc, bi), 0.f);
        *reinterpret_cast<float2*>(&s_a2[p * 68 + 2 * c]) = o;
    }
    __syncthreads();

    int lane = t & 31, wid = t >> 5;
    int p = wid * 32 + lane;
    int pc = p < 169 ? p : 168;

    ull a2r[32];
    {
        const ulonglong2* row = reinterpret_cast<const ulonglong2*>(&s_a2[pc * 68]);
#pragma unroll
        for (int i = 0; i < 16; i++) {
            ulonglong2 v = row[i];
            a2r[2 * i] = v.x; a2r[2 * i + 1] = v.y;
        }
    }
    float o0[10], o1[10];
#pragma unroll
    for (int j = 0; j < 10; j++) { o0[j] = 0.f; o1[j] = 0.f; }
    const float4* fwp = reinterpret_cast<const float4*>(g_fcwp);

    for (int c3 = 0; c3 < 64; c3++) {
        const ulonglong2* wr = reinterpret_cast<const ulonglong2*>(&s_wd[c3 * 64]);
        ull acc0 = pk2(0.f, 0.f), acc1 = acc0, acc2 = acc0, acc3 = acc0;
#pragma unroll
        for (int i = 0; i < 8; i++) {
            ulonglong2 va = wr[2 * i];
            ulonglong2 vb = wr[2 * i + 1];
            FMA2(acc0, a2r[4 * i],     va.x);
            FMA2(acc1, a2r[4 * i + 1], va.y);
            FMA2(acc2, a2r[4 * i + 2], vb.x);
            FMA2(acc3, a2r[4 * i + 3], vb.y);
        }
        float e0, e1, e2, e3, f0, f1, f2, f3;
        upk2(acc0, e0, f0); upk2(acc1, e1, f1);
        upk2(acc2, e2, f2); upk2(acc3, e3, f3);
        float sc = s_bn3[c3], bi = s_bn3[64 + c3];
        float v0 = fmaxf(fmaf((e0 + e1) + (e2 + e3), sc, bi), 0.f);   // image 0
        float v1 = fmaxf(fmaf((f0 + f1) + (f2 + f3), sc, bi), 0.f);   // image 1
        int base = (c3 * 169 + pc) * 3;
        float4 w0 = fwp[base], w1 = fwp[base + 1], w2 = fwp[base + 2];
        o0[0] += v0 * w0.x; o1[0] += v1 * w0.x;
        o0[1] += v0 * w0.y; o1[1] += v1 * w0.y;
        o0[2] += v0 * w0.z; o1[2] += v1 * w0.z;
        o0[3] += v0 * w0.w; o1[3] += v1 * w0.w;
        o0[4] += v0 * w1.x; o1[4] += v1 * w1.x;
        o0[5] += v0 * w1.y; o1[5] += v1 * w1.y;
        o0[6] += v0 * w1.z; o1[6] += v1 * w1.z;
        o0[7] += v0 * w1.w; o1[7] += v1 * w1.w;
        o0[8] += v0 * w2.x; o1[8] += v1 * w2.x;
        o0[9] += v0 * w2.y; o1[9] += v1 * w2.y;
    }
#pragma unroll
    for (int j = 0; j < 10; j++) {
        if (p >= 169) { o0[j] = 0.f; o1[j] = 0.f; }
#pragma unroll
        for (int off = 16; off > 0; off >>= 1) {
            o0[j] += __shfl_xor_sync(0xffffffffu, o0[j], off);
            o1[j] += __shfl_xor_sync(0xffffffffu, o1[j], off);
        }
    }
    if (lane == 0) {
#pragma unroll
        for (int j = 0; j < 10; j++) {
            atomicAdd(&s_out[j],      o0[j]);
            atomicAdd(&s_out[10 + j], o1[j]);
        }
    }
    __syncthreads();
    if (t < 20) {
        int im = t / 10, j = t - im * 10;
        out[(pair * 2 + im) * 10 + j] = s_out[im * 10 + j] + fc_b[j];
    }
}

// ---------------- launch ----------------
extern "C" void kernel_launch(void* const* d_in, const int* in_sizes, int n_in,
                              void* d_out, int out_size) {
    const float* x    = (const float*)d_in[0];
    const float* w1   = (const float*)d_in[1];
    const float* w2   = (const float*)d_in[2];
    const float* w3   = (const float*)d_in[3];
    const float* g1   = (const float*)d_in[4];
    const float* b1   = (const float*)d_in[5];
    const float* g2   = (const float*)d_in[6];
    const float* b2   = (const float*)d_in[7];
    const float* g3   = (const float*)d_in[8];
    const float* b3   = (const float*)d_in[9];
    const float* fc_w = (const float*)d_in[10];
    const float* fc_b = (const float*)d_in[11];
    float* out = (float*)d_out;

    const int c2_smem  = 73216;                     // A tiles + out buffers
    const int fin_smem = (169 * 68 + 4096) * 4;     // 62352
    cudaFuncSetAttribute(k_conv2, cudaFuncAttributeMaxDynamicSharedMemorySize, c2_smem);
    cudaFuncSetAttribute(k_final, cudaFuncAttributeMaxDynamicSharedMemorySize, fin_smem);

    k_zero<<<1, 1024>>>();
    k_packfc<<<43, 256>>>(fc_w);
    k_conv1<<<2048, 256>>>(x, w1);
    k_finalize<<<1, 64>>>(0, g1, b1);
    k_conv2<<<2048, 256, c2_smem>>>(w2);
    k_finalize<<<1, 64>>>(1, g2, b2);
    k_gram<<<2048, 256>>>();
    k_fin3<<<1, 64>>>(w3, g3, b3);
    k_final<<<NPAIR, FIN_THREADS, fin_smem>>>(w3, fc_b, out);
}